// round 3
// baseline (speedup 1.0000x reference)
#include <cuda_runtime.h>
#include <cuda_bf16.h>
#include <cstdint>

#define CB   2
#define CC   128
#define CH   20
#define CW   20
#define CHW  400
#define CEPS 1e-5f

typedef unsigned long long ull;

// ---------------- device scratch ----------------
__device__ float g_w1t[CC * CC];        // [k][c] folded w1
__device__ float g_bias1[CC];
__device__ float g_w2t[CC * CC];        // [k][c] folded w2
__device__ float g_bias2[CC];
__device__ float g_wr1ft[256 * CC];     // [c'][o] folded wr1 (transposed)
__device__ float g_biasr1[CC];
__device__ float g_wconv[9 * CC * CC];  // [(c*9+k)*128 + c2] folded wr2
__device__ float g_biasr2[CC];
__device__ float g_T[9 * CC * CC];      // [cls][o][o2] border-class tap sums of folded wr2
__device__ float g_wr3[CC];
__device__ float g_bias3s[1];
__device__ float g_A0[200 * CC];        // per fj-row group-0 weight colsum
__device__ float g_A1[200 * CC];
__device__ float g_feat[CB * CHW * CC];   // [b][j][c]
__device__ float g_featT[CB * CC * CHW];  // [b][c][j]
__device__ float g_scores[CB * CHW * CHW];

struct Params { const float* p[26]; };

__device__ __forceinline__ float siluf(float x) {
    float s = 1.f / (1.f + __expf(-x));
    return x * s;
}
__device__ __forceinline__ ull pack2(float x, float y) {
    ull r; asm("mov.b64 %0, {%1,%2};" : "=l"(r) : "f"(x), "f"(y)); return r;
}
__device__ __forceinline__ void unpack2(ull v, float& x, float& y) {
    asm("mov.b64 {%0,%1}, %2;" : "=f"(x), "=f"(y) : "l"(v));
}
__device__ __forceinline__ void ffma2(ull& d, ull a, ull b) {
    asm("fma.rn.f32x2 %0, %1, %2, %0;" : "+l"(d) : "l"(a), "l"(b));
}

// ---------------- K0: fold BN into weights ----------------
__global__ void fold_kernel(Params P) {
    const float* w1  = P.p[1];
    const float* g1  = P.p[2];  const float* b1 = P.p[3];
    const float* m1  = P.p[4];  const float* v1 = P.p[5];
    const float* w2  = P.p[6];
    const float* g2  = P.p[7];  const float* b2 = P.p[8];
    const float* m2  = P.p[9];  const float* v2 = P.p[10];
    const float* wr1 = P.p[11];
    const float* gr1 = P.p[12]; const float* br1 = P.p[13];
    const float* mr1 = P.p[14]; const float* vr1 = P.p[15];
    const float* wr2 = P.p[16];
    const float* gr2 = P.p[17]; const float* br2 = P.p[18];
    const float* mr2 = P.p[19]; const float* vr2 = P.p[20];
    const float* wr3 = P.p[21];
    const float* gr3 = P.p[22]; const float* br3 = P.p[23];
    const float* mr3 = P.p[24]; const float* vr3 = P.p[25];

    int t = blockIdx.x * blockDim.x + threadIdx.x;
    int stride = gridDim.x * blockDim.x;

    for (int i = t; i < CC * CC; i += stride) {
        int c = i >> 7, k = i & 127;
        float s  = g1[c] * rsqrtf(v1[c] + CEPS);
        g_w1t[k * CC + c] = w1[i] * s;
        float s2 = g2[c] * rsqrtf(v2[c] + CEPS);
        g_w2t[k * CC + c] = w2[i] * s2;
    }
    // wr1ft[c'][o] = wr1[o][c'] * scale(o)
    for (int i = t; i < 256 * CC; i += stride) {
        int cp = i >> 7, o = i & 127;
        float sr = gr1[o] * rsqrtf(vr1[o] + CEPS);
        g_wr1ft[cp * CC + o] = wr1[o * 256 + cp] * sr;
    }
    // folded wr2 in [(c*9+k)*128 + c2] layout
    for (int i = t; i < 9 * CC * CC; i += stride) {
        int c2 = i / 1152; int r = i - c2 * 1152;
        int c = r / 9; int k9 = r - c * 9;
        float s = gr2[c2] * rsqrtf(vr2[c2] + CEPS);
        g_wconv[(c * 9 + k9) * CC + c2] = wr2[i] * s;
    }
    // border-class tap sums: T[cls][o][o2]
    for (int i = t; i < 9 * CC * CC; i += stride) {
        int cls = i >> 14; int r = i & 16383;
        int o = r >> 7; int o2 = r & 127;
        int rc = cls / 3, ccl = cls - rc * 3;
        float s = gr2[o2] * rsqrtf(vr2[o2] + CEPS);
        float acc = 0.f;
        #pragma unroll
        for (int k = 0; k < 9; k++) {
            int ky = k / 3, kx = k - ky * 3;
            bool rok = (rc == 1) || (rc == 0 ? (ky >= 1) : (ky <= 1));
            bool cok = (ccl == 1) || (ccl == 0 ? (kx >= 1) : (kx <= 1));
            if (rok && cok) acc += wr2[(o2 * CC + o) * 9 + k];
        }
        g_T[i] = acc * s;
    }
    if (t < CC) {
        float s1 = g1[t] * rsqrtf(v1[t] + CEPS);
        g_bias1[t] = b1[t] - s1 * m1[t];
        float s2 = g2[t] * rsqrtf(v2[t] + CEPS);
        g_bias2[t] = b2[t] - s2 * m2[t];
        float sr1 = gr1[t] * rsqrtf(vr1[t] + CEPS);
        g_biasr1[t] = br1[t] - sr1 * mr1[t];
        float sr2 = gr2[t] * rsqrtf(vr2[t] + CEPS);
        g_biasr2[t] = br2[t] - sr2 * mr2[t];
        float s3 = gr3[0] * rsqrtf(vr3[0] + CEPS);
        g_wr3[t] = wr3[t] * s3;
        if (t == 0) g_bias3s[0] = br3[0] - s3 * mr3[0];
    }
}

// ---------------- K0b: per-fj-row weight column-sums ----------------
__global__ __launch_bounds__(128) void a0_kernel() {
    int nb = 200 + blockIdx.x;     // 200..399
    int o = threadIdx.x;
    int s = nb * 256;
    int rem = s % 400;
    int g0 = 400 - rem; if (g0 > 256) g0 = 256;   // rem==0 -> 400 -> clamp 256
    float a0 = 0.f, a1 = 0.f;
    for (int cp = 0; cp < 256; cp++) {
        float w = g_wr1ft[cp * CC + o];
        if (cp < g0) a0 += w; else a1 += w;
    }
    g_A0[blockIdx.x * CC + o] = a0;
    g_A1[blockIdx.x * CC + o] = a1;
}

// ---------------- K1: feat = CBS1(x) ----------------
__global__ __launch_bounds__(128) void feat_kernel(const float* __restrict__ x) {
    __shared__ float xs[CC];
    int bj = blockIdx.x;
    int b = bj / CHW; int j = bj - b * CHW;
    int c = threadIdx.x;
    xs[c] = x[(b * CC + c) * CHW + j];
    __syncthreads();
    float acc = g_bias1[c];
    #pragma unroll 8
    for (int k = 0; k < CC; k++) acc += g_w1t[k * CC + c] * xs[k];
    float f = siluf(acc);
    g_feat[bj * CC + c] = f;
    g_featT[(b * CC + c) * CHW + j] = f;
}

// ---------------- K2: fi rows (n_b < 200): spatially-constant input ----------------
__global__ __launch_bounds__(128) void relation_fi_kernel() {
    __shared__ float gs[256];
    __shared__ float r1s[CC];
    __shared__ float red[9 * CC];
    __shared__ float sval[9];

    int bi = blockIdx.x;
    int b = bi / 200; int nb = bi - b * 200;   // i_s = nb in [0,200)
    int t = threadIdx.x;

    // input vector = contiguous slice of featT
    const float* src = g_featT + b * (CC * CHW) + nb * 256;
    gs[t] = src[t]; gs[t + 128] = src[t + 128];
    __syncthreads();

    // conv1 (1x1): 256 -> 128 matvec + silu
    float acc = g_biasr1[t];
    #pragma unroll 8
    for (int cp = 0; cp < 256; cp++) acc += g_wr1ft[cp * CC + t] * gs[cp];
    r1s[t] = siluf(acc);
    __syncthreads();

    // conv2 (3x3 on constant image): 9 border classes via tap-sum table
    float acc9[9];
    float br2 = g_biasr2[t];
    #pragma unroll
    for (int cls = 0; cls < 9; cls++) acc9[cls] = br2;
    for (int o = 0; o < CC; o++) {
        float r = r1s[o];
        int base = o * CC + t;
        #pragma unroll
        for (int cls = 0; cls < 9; cls++)
            acc9[cls] += g_T[cls * (CC * CC) + base] * r;
    }
    float w3 = g_wr3[t];
    #pragma unroll
    for (int cls = 0; cls < 9; cls++) red[cls * CC + t] = w3 * siluf(acc9[cls]);
    __syncthreads();
    if (t < 9) {
        float s = g_bias3s[0];
        for (int o2 = 0; o2 < CC; o2++) s += red[t * CC + o2];
        sval[t] = siluf(s);
    }
    __syncthreads();

    float* out = g_scores + (b * CHW + nb) * CHW;
    for (int j = t; j < CHW; j += 128) {
        int y = j / CW, xp = j - y * CW;
        int rc = (y == 0) ? 0 : (y == CH - 1 ? 2 : 1);
        int ccl = (xp == 0) ? 0 : (xp == CW - 1 ? 2 : 1);
        out[j] = sval[rc * 3 + ccl];
    }
}

// ---------------- K3: fj rows (n_b >= 200): heavy 3x3 conv ----------------
#define R1N    (CC * CHW)          // 51200
#define R1PAD  (R1N + 4)
#define WBUFN  (8 * 9 * 16)        // 1152
#define R_SMEM_FLOATS (R1PAD + WBUFN + 3 * CC + 2 * CHW)

__global__ __launch_bounds__(256, 1) void relation_fj_kernel() {
    extern __shared__ float sm[];
    float* r1s  = sm;
    float* wbuf = sm + R1PAD;
    float* A0s  = wbuf + WBUFN;
    float* A1s  = A0s + CC;
    float* bs   = A1s + CC;
    float* f0s  = bs + CC;
    float* f1s  = f0s + CHW;

    int bi = blockIdx.x;
    int b = bi / 200; int nbr = bi - b * 200;   // row index relative; nb = 200+nbr
    int nb = 200 + nbr;
    int t = threadIdx.x;

    int s = nb * 256;
    int rem = s % 400;
    int g0 = 400 - rem; if (g0 > 256) g0 = 256;
    int cc0 = s / 400 - 128;
    int cc1 = (g0 < 256) ? (cc0 + 1) : cc0;

    if (t < CC) {
        A0s[t] = g_A0[nbr * CC + t];
        A1s[t] = g_A1[nbr * CC + t];
        bs[t]  = g_biasr1[t];
    }
    {
        const float* f0p = g_featT + (b * CC + cc0) * CHW;
        const float* f1p = g_featT + (b * CC + cc1) * CHW;
        if (t < CHW) { f0s[t] = f0p[t]; f1s[t] = f1p[t]; }
        int t2 = t + 256;
        if (t2 < CHW) { f0s[t2] = f0p[t2]; f1s[t2] = f1p[t2]; }
    }
    if (t == 0) { r1s[R1N] = 0.f; r1s[R1N+1] = 0.f; r1s[R1N+2] = 0.f; r1s[R1N+3] = 0.f; }
    __syncthreads();

    // phase 1: r1[c][j] = silu(A0[c]*f0[j] + A1[c]*f1[j] + b[c])
    for (int c = 0; c < CC; c++) {
        float a0 = A0s[c], a1 = A1s[c], bb = bs[c];
        int base = c * CHW;
        r1s[base + t] = siluf(fmaf(a0, f0s[t], fmaf(a1, f1s[t], bb)));
        int t2 = t + 256;
        if (t2 < CHW) r1s[base + t2] = siluf(fmaf(a0, f0s[t2], fmaf(a1, f1s[t2], bb)));
    }
    __syncthreads();

    // phase 2: 3x3 conv (16 c2-tile x 2 pixels/thread) + final 1x1 reduce
    int p0 = t, p1 = t + 256;
    bool h1 = (p1 < CHW);
    int y0 = p0 / CW, x0 = p0 - y0 * CW;
    int y1 = h1 ? p1 / CW : 0, x1 = h1 ? (p1 - (p1 / CW) * CW) : 0;

    int nb0[9], nb1[9];
    #pragma unroll
    for (int ky = 0; ky < 3; ky++) {
        #pragma unroll
        for (int kx = 0; kx < 3; kx++) {
            int k = ky * 3 + kx;
            int yy = y0 + ky - 1, xx = x0 + kx - 1;
            nb0[k] = (yy >= 0 && yy < CH && xx >= 0 && xx < CW) ? yy * CW + xx : -1;
            int yy1 = y1 + ky - 1, xx1 = x1 + kx - 1;
            nb1[k] = (h1 && yy1 >= 0 && yy1 < CH && xx1 >= 0 && xx1 < CW) ? yy1 * CW + xx1 : -1;
        }
    }

    float bias3 = g_bias3s[0];
    float sc0 = bias3, sc1 = bias3;

    for (int c2t = 0; c2t < CC; c2t += 16) {
        ull a0[8], a1[8];
        const ull* bp = reinterpret_cast<const ull*>(g_biasr2 + c2t);
        #pragma unroll
        for (int q = 0; q < 8; q++) { a0[q] = bp[q]; a1[q] = bp[q]; }

        for (int cb = 0; cb < CC; cb += 8) {
            __syncthreads();
            for (int widx = t; widx < WBUFN; widx += 256) {
                int cp = widx / 144; int r = widx - cp * 144;
                int k = r >> 4; int c2p = r & 15;
                wbuf[widx] = g_wconv[((cb + cp) * 9 + k) * CC + c2t + c2p];
            }
            __syncthreads();

            #pragma unroll 1
            for (int cc = 0; cc < 8; cc++) {
                int cbase = (cb + cc) * CHW;
                const float* wrow = wbuf + cc * 144;
                #pragma unroll
                for (int k = 0; k < 9; k++) {
                    int o0 = nb0[k]; int i0 = (o0 >= 0) ? cbase + o0 : R1N;
                    int o1 = nb1[k]; int i1 = (o1 >= 0) ? cbase + o1 : R1N;
                    float v0f = r1s[i0];
                    float v1f = r1s[i1];
                    ull v0 = pack2(v0f, v0f);
                    ull v1 = pack2(v1f, v1f);
                    const ulonglong2* wp = reinterpret_cast<const ulonglong2*>(wrow + k * 16);
                    ulonglong2 wA = wp[0], wB = wp[1], wC = wp[2], wD = wp[3];
                    ffma2(a0[0], wA.x, v0); ffma2(a0[1], wA.y, v0);
                    ffma2(a0[2], wB.x, v0); ffma2(a0[3], wB.y, v0);
                    ffma2(a0[4], wC.x, v0); ffma2(a0[5], wC.y, v0);
                    ffma2(a0[6], wD.x, v0); ffma2(a0[7], wD.y, v0);
                    ffma2(a1[0], wA.x, v1); ffma2(a1[1], wA.y, v1);
                    ffma2(a1[2], wB.x, v1); ffma2(a1[3], wB.y, v1);
                    ffma2(a1[4], wC.x, v1); ffma2(a1[5], wC.y, v1);
                    ffma2(a1[6], wD.x, v1); ffma2(a1[7], wD.y, v1);
                }
            }
        }

        #pragma unroll
        for (int q = 0; q < 8; q++) {
            float lo, hi;
            float w3a = g_wr3[c2t + 2 * q], w3b = g_wr3[c2t + 2 * q + 1];
            unpack2(a0[q], lo, hi);
            sc0 += w3a * siluf(lo) + w3b * siluf(hi);
            unpack2(a1[q], lo, hi);
            sc1 += w3a * siluf(lo) + w3b * siluf(hi);
        }
    }

    float* out = g_scores + (b * CHW + nb) * CHW;
    out[p0] = siluf(sc0);
    if (h1) out[p1] = siluf(sc1);
}

// ---------------- K4: att = scores @ feat ; out = CBS2(att) + x ----------------
__global__ __launch_bounds__(128) void att_kernel(const float* __restrict__ x,
                                                  float* __restrict__ out) {
    __shared__ float sc[CHW];
    __shared__ float at[CC];
    int bi = blockIdx.x;
    int b = bi / CHW; int i = bi - b * CHW;
    int t = threadIdx.x;
    for (int j = t; j < CHW; j += 128) sc[j] = g_scores[bi * CHW + j];
    __syncthreads();
    float acc = 0.f;
    const float* fb = g_feat + b * CHW * CC;
    #pragma unroll 4
    for (int j = 0; j < CHW; j++) acc += sc[j] * fb[j * CC + t];
    at[t] = acc;
    __syncthreads();
    float o = g_bias2[t];
    #pragma unroll 8
    for (int k = 0; k < CC; k++) o += g_w2t[k * CC + t] * at[k];
    int oi = (b * CC + t) * CHW + i;
    out[oi] = siluf(o) + x[oi];
}

// ---------------- launch ----------------
extern "C" void kernel_launch(void* const* d_in, const int* in_sizes, int n_in,
                              void* d_out, int out_size) {
    (void)in_sizes; (void)n_in; (void)out_size;
    Params P;
    for (int i = 0; i < 26; i++) P.p[i] = (const float*)d_in[i];
    const float* x = (const float*)d_in[0];
    float* out = (float*)d_out;

    fold_kernel<<<64, 256>>>(P);
    a0_kernel<<<200, 128>>>();
    feat_kernel<<<CB * CHW, 128>>>(x);
    relation_fi_kernel<<<CB * 200, 128>>>();

    static const int R_SMEM = R_SMEM_FLOATS * sizeof(float);
    cudaFuncSetAttribute((const void*)relation_fj_kernel,
                         cudaFuncAttributeMaxDynamicSharedMemorySize, R_SMEM);
    relation_fj_kernel<<<CB * 200, 256, R_SMEM>>>();

    att_kernel<<<CB * CHW, 128>>>(x, out);
}

// round 5
// speedup vs baseline: 6.9958x; 6.9958x over previous
#include <cuda_runtime.h>
#include <cuda_bf16.h>
#include <cstdint>

#define CB   2
#define CC   128
#define CH   20
#define CW   20
#define CHW  400
#define CEPS 1e-5f

// ======================= helpers =======================
__device__ __forceinline__ uint32_t smem_to_u32(const void* p) {
    uint32_t a;
    asm("{ .reg .u64 t; cvta.to.shared.u64 t, %1; cvt.u32.u64 %0, t; }" : "=r"(a) : "l"(p));
    return a;
}
__device__ __forceinline__ void ldsm_x4(unsigned* r, uint32_t addr) {
    asm volatile("ldmatrix.sync.aligned.m8n8.x4.shared.b16 {%0,%1,%2,%3}, [%4];"
        : "=r"(r[0]), "=r"(r[1]), "=r"(r[2]), "=r"(r[3]) : "r"(addr));
}
__device__ __forceinline__ void mma16816(float* d, const unsigned* a, const unsigned* b) {
    asm volatile("mma.sync.aligned.m16n8k16.row.col.f32.bf16.bf16.f32 "
        "{%0,%1,%2,%3}, {%4,%5,%6,%7}, {%8,%9}, {%0,%1,%2,%3};"
        : "+f"(d[0]), "+f"(d[1]), "+f"(d[2]), "+f"(d[3])
        : "r"(a[0]), "r"(a[1]), "r"(a[2]), "r"(a[3]), "r"(b[0]), "r"(b[1]));
}

// ======================= device scratch =======================
__device__ float g_w1t[CC * CC];
__device__ float g_bias1[CC];
__device__ float g_w2t[CC * CC];
__device__ float g_bias2[CC];
__device__ float g_wr1ft[256 * CC];
__device__ float g_biasr1[CC];
__device__ float g_T[9 * CC * CC];
__device__ float g_biasr2[CC];
__device__ float g_wr3[CC];
__device__ float g_bias3s[1];
__device__ float g_A0[200 * CC];
__device__ float g_A1[200 * CC];
__device__ float g_feat[CB * CHW * CC];
__device__ float g_featT[CB * CC * CHW];
__device__ float g_scores[CB * CHW * CHW];
__device__ __align__(16) __nv_bfloat16 g_wcv[9 * CC * CC]; // [tap][c2][ch] folded bf16
__device__ float2 g_lut[2048];

struct Params { const float* p[26]; };

__device__ __forceinline__ float siluf(float x) {
    float s = 1.f / (1.f + __expf(-x));
    return x * s;
}
__device__ __forceinline__ float lut_silu(const float2* lut, float x) {
    float xc = fminf(fmaxf(x, -16.0f), 15.99993f);
    float fi = (xc + 16.0f) * 64.0f;
    int i = (int)fi;
    float fr = fi - (float)i;
    float2 e = lut[i];
    float y = fmaf(fr, e.y, e.x);
    return (x >= 16.0f) ? x : y;
}

// ======================= K0: fold =======================
__global__ void fold_kernel(Params P) {
    const float* w1  = P.p[1];
    const float* g1  = P.p[2];  const float* b1 = P.p[3];
    const float* m1  = P.p[4];  const float* v1 = P.p[5];
    const float* w2  = P.p[6];
    const float* g2  = P.p[7];  const float* b2 = P.p[8];
    const float* m2  = P.p[9];  const float* v2 = P.p[10];
    const float* wr1 = P.p[11];
    const float* gr1 = P.p[12]; const float* br1 = P.p[13];
    const float* mr1 = P.p[14]; const float* vr1 = P.p[15];
    const float* wr2 = P.p[16];
    const float* gr2 = P.p[17]; const float* br2 = P.p[18];
    const float* mr2 = P.p[19]; const float* vr2 = P.p[20];
    const float* wr3 = P.p[21];
    const float* gr3 = P.p[22]; const float* br3 = P.p[23];
    const float* mr3 = P.p[24]; const float* vr3 = P.p[25];

    int t = blockIdx.x * blockDim.x + threadIdx.x;
    int stride = gridDim.x * blockDim.x;

    for (int i = t; i < CC * CC; i += stride) {
        int c = i >> 7, k = i & 127;
        float s  = g1[c] * rsqrtf(v1[c] + CEPS);
        g_w1t[k * CC + c] = w1[i] * s;
        float s2 = g2[c] * rsqrtf(v2[c] + CEPS);
        g_w2t[k * CC + c] = w2[i] * s2;
    }
    for (int i = t; i < 256 * CC; i += stride) {
        int cp = i >> 7, o = i & 127;
        float sr = gr1[o] * rsqrtf(vr1[o] + CEPS);
        g_wr1ft[cp * CC + o] = wr1[o * 256 + cp] * sr;
    }
    // conv weights bf16 [tap][c2][ch]
    for (int i = t; i < 9 * CC * CC; i += stride) {
        int di = i >> 14; int r = i & 16383;
        int c2 = r >> 7; int c = r & 127;
        float s = gr2[c2] * rsqrtf(vr2[c2] + CEPS);
        g_wcv[i] = __float2bfloat16(wr2[(c2 * CC + c) * 9 + di] * s);
    }
    // silu LUT
    for (int i = t; i < 2048; i += stride) {
        float x0 = -16.0f + (float)i * 0.015625f;
        float x1 = x0 + 0.015625f;
        float s0 = x0 / (1.0f + expf(-x0));
        float s1 = x1 / (1.0f + expf(-x1));
        g_lut[i] = make_float2(s0, s1 - s0);
    }
    // border-class tap sums for fi path
    for (int i = t; i < 9 * CC * CC; i += stride) {
        int cls = i >> 14; int r = i & 16383;
        int o = r >> 7; int o2 = r & 127;
        int rc = cls / 3, ccl = cls - rc * 3;
        float s = gr2[o2] * rsqrtf(vr2[o2] + CEPS);
        float acc = 0.f;
        #pragma unroll
        for (int k = 0; k < 9; k++) {
            int ky = k / 3, kx = k - ky * 3;
            bool rok = (rc == 1) || (rc == 0 ? (ky >= 1) : (ky <= 1));
            bool cok = (ccl == 1) || (ccl == 0 ? (kx >= 1) : (kx <= 1));
            if (rok && cok) acc += wr2[(o2 * CC + o) * 9 + k];
        }
        g_T[i] = acc * s;
    }
    if (t < CC) {
        float s1 = g1[t] * rsqrtf(v1[t] + CEPS);
        g_bias1[t] = b1[t] - s1 * m1[t];
        float s2 = g2[t] * rsqrtf(v2[t] + CEPS);
        g_bias2[t] = b2[t] - s2 * m2[t];
        float sr1 = gr1[t] * rsqrtf(vr1[t] + CEPS);
        g_biasr1[t] = br1[t] - sr1 * mr1[t];
        float sr2 = gr2[t] * rsqrtf(vr2[t] + CEPS);
        g_biasr2[t] = br2[t] - sr2 * mr2[t];
        float s3 = gr3[0] * rsqrtf(vr3[0] + CEPS);
        g_wr3[t] = wr3[t] * s3;
        if (t == 0) g_bias3s[0] = br3[0] - s3 * mr3[0];
    }
}

// ======================= K0b: per-fj-row column sums =======================
__global__ __launch_bounds__(128) void a0_kernel() {
    int nb = 200 + blockIdx.x;
    int o = threadIdx.x;
    int s = nb * 256;
    int rem = s % 400;
    int g0 = 400 - rem; if (g0 > 256) g0 = 256;
    float a0 = 0.f, a1 = 0.f;
    for (int cp = 0; cp < 256; cp++) {
        float w = g_wr1ft[cp * CC + o];
        if (cp < g0) a0 += w; else a1 += w;
    }
    g_A0[blockIdx.x * CC + o] = a0;
    g_A1[blockIdx.x * CC + o] = a1;
}

// ======================= K1: feat =======================
__global__ __launch_bounds__(128) void feat_kernel(const float* __restrict__ x) {
    __shared__ float xs[CC];
    int bj = blockIdx.x;
    int b = bj / CHW; int j = bj - b * CHW;
    int c = threadIdx.x;
    xs[c] = x[(b * CC + c) * CHW + j];
    __syncthreads();
    float acc = g_bias1[c];
    #pragma unroll 8
    for (int k = 0; k < CC; k++) acc += g_w1t[k * CC + c] * xs[k];
    float f = siluf(acc);
    g_feat[bj * CC + c] = f;
    g_featT[(b * CC + c) * CHW + j] = f;
}

// ======================= K2: fi rows =======================
__global__ __launch_bounds__(256) void relation_fi_kernel() {
    __shared__ float gs[256];
    __shared__ float part[128];
    __shared__ float r1s[128];
    __shared__ float red2[9 * 128];
    __shared__ float redw[9 * 128];
    __shared__ float sval[9];

    int bi = blockIdx.x;
    int b = bi / 200; int nb = bi - b * 200;
    int t = threadIdx.x;
    int o = t & 127; int hb = t >> 7;

    const float* src = g_featT + b * (CC * CHW) + nb * 256;
    gs[t] = src[t];
    __syncthreads();

    float acc = hb ? 0.f : g_biasr1[o];
    int cp0 = hb * 128;
    #pragma unroll 8
    for (int cp = cp0; cp < cp0 + 128; cp++) acc += g_wr1ft[cp * CC + o] * gs[cp];
    if (hb) part[o] = acc;
    __syncthreads();
    if (!hb) r1s[o] = siluf(acc + part[o]);
    __syncthreads();

    float acc9[9];
    float bz = hb ? 0.f : g_biasr2[o];
    #pragma unroll
    for (int cls = 0; cls < 9; cls++) acc9[cls] = bz;
    int ob = hb * 64;
    for (int oo = ob; oo < ob + 64; oo++) {
        float r = r1s[oo];
        int base = oo * CC + o;
        #pragma unroll
        for (int cls = 0; cls < 9; cls++)
            acc9[cls] = fmaf(g_T[cls * (CC * CC) + base], r, acc9[cls]);
    }
    if (hb) {
        #pragma unroll
        for (int cls = 0; cls < 9; cls++) red2[cls * 128 + o] = acc9[cls];
    }
    __syncthreads();
    if (!hb) {
        float w3 = g_wr3[o];
        #pragma unroll
        for (int cls = 0; cls < 9; cls++)
            redw[cls * 128 + o] = w3 * siluf(acc9[cls] + red2[cls * 128 + o]);
    }
    __syncthreads();
    if (t < 9) {
        float s = g_bias3s[0];
        for (int o2 = 0; o2 < 128; o2++) s += redw[t * 128 + o2];
        sval[t] = siluf(s);
    }
    __syncthreads();

    float* out = g_scores + (b * CHW + nb) * CHW;
    for (int j = t; j < CHW; j += 256) {
        int y = j / CW, xp = j - y * CW;
        int rc = (y == 0) ? 0 : (y == CH - 1 ? 2 : 1);
        int ccl = (xp == 0) ? 0 : (xp == CW - 1 ? 2 : 1);
        out[j] = sval[rc * 3 + ccl];
    }
}

// ======================= K3: fj rows via mma.sync bf16 =======================
// pitch 272B rows (68 words ≡ 4 banks mod 32 -> conflict-free ldmatrix)
#define PITCH 272
#define OFF_A0    0
#define OFF_A1    512
#define OFF_BS    1024
#define OFF_BR2   1536
#define OFF_W3    2048
#define OFF_B3    2560
#define OFF_PART  2576                  // 512 floats
#define OFF_F0    (OFF_PART + 2048)     // 4624
#define OFF_F1    (OFF_F0 + 1600)       // 6224
#define OFF_LUT   (OFF_F1 + 1600)       // 7824, 16384 bytes
#define OFF_WST   (OFF_LUT + 16384)     // 24208, 64*272 = 17408
#define OFF_R1P   (OFF_WST + 17408)     // 41616, 558*272 = 151776
#define FJ_SMEM   (OFF_R1P + 151776)    // 193392

__global__ __launch_bounds__(256, 1) void relation_fj_mma_kernel() {
    extern __shared__ char smem[];
    uint32_t sbase = smem_to_u32(smem);
    float* a0s  = (float*)(smem + OFF_A0);
    float* a1s  = (float*)(smem + OFF_A1);
    float* bss  = (float*)(smem + OFF_BS);
    float* br2s = (float*)(smem + OFF_BR2);
    float* w3s  = (float*)(smem + OFF_W3);
    float* b3s  = (float*)(smem + OFF_B3);
    float* part = (float*)(smem + OFF_PART);
    float* f0s  = (float*)(smem + OFF_F0);
    float* f1s  = (float*)(smem + OFF_F1);
    const float2* lutp = (const float2*)(smem + OFF_LUT);
    char* r1pb = smem + OFF_R1P;

    int bi = blockIdx.x;
    int b = bi / 200; int nbr = bi - b * 200;
    int nb = 200 + nbr;
    int t = threadIdx.x;
    int w = t >> 5;
    int lane = t & 31;

    // per-row constants
    int s = nb * 256;
    int rem = s % 400;
    int g0 = 400 - rem; if (g0 > 256) g0 = 256;
    int cc0 = s / 400 - 128;
    int cc1 = (g0 < 256) ? (cc0 + 1) : cc0;

    if (t < CC) {
        a0s[t] = g_A0[nbr * CC + t];
        a1s[t] = g_A1[nbr * CC + t];
        bss[t] = g_biasr1[t];
        br2s[t] = g_biasr2[t];
        w3s[t] = g_wr3[t];
        if (t == 0) b3s[0] = g_bias3s[0];
    }
    {
        const float* f0p = g_featT + (b * CC + cc0) * CHW;
        const float* f1p = g_featT + (b * CC + cc1) * CHW;
        for (int j = t; j < CHW; j += 256) { f0s[j] = f0p[j]; f1s[j] = f1p[j]; }
    }
    for (int i = t; i < 2048; i += 256)
        ((float2*)(smem + OFF_LUT))[i] = g_lut[i];

    // zero r1p (incl. pad bytes)
    for (int i = t; i < (558 * PITCH) / 16; i += 256)
        ((uint4*)r1pb)[i] = make_uint4(0, 0, 0, 0);
    __syncthreads();

    // phase 1: interior fill r1[u=23+q][c] = silu(a0*f0 + a1*f1 + b), bf16 pairs
    for (int idx = t; idx < 400 * 64; idx += 256) {
        int j = idx >> 6, cp = idx & 63; int c = cp * 2;
        int y = j / 20, xx = j - y * 20;
        int u = 23 + (y + 1) * 22 + (xx + 1);
        float f0 = f0s[j], f1 = f1s[j];
        float t0 = fmaf(a0s[c], f0, fmaf(a1s[c], f1, bss[c]));
        float t1 = fmaf(a0s[c + 1], f0, fmaf(a1s[c + 1], f1, bss[c + 1]));
        __nv_bfloat162 h2 = __floats2bfloat162_rn(lut_silu(lutp, t0), lut_silu(lutp, t1));
        *(unsigned*)(r1pb + u * PITCH + cp * 4) = *(unsigned*)&h2;
    }

    // fragment address components
    int lrow = lane & 15;            // A row within m16
    int lcol = lane >> 4;            // A 16B col half
    int brow = (lane & 7) + ((lane >> 4) << 3);   // B row (n) within 16
    int bcol = ((lane >> 3) & 1) * 16;            // B 16B col half
    uint32_t r1addr = sbase + OFF_R1P;
    uint32_t wstaddr = sbase + OFF_WST;

    float bias3 = 0.f;

    for (int npass = 0; npass < 2; npass++) {
        float acc[4][8][4];
        #pragma unroll
        for (int mf = 0; mf < 4; mf++)
            #pragma unroll
            for (int nf = 0; nf < 8; nf++)
                #pragma unroll
                for (int q = 0; q < 4; q++) acc[mf][nf][q] = 0.f;

        for (int tap = 0; tap < 9; tap++) {
            __syncthreads();
            // stage W half: rows c2 = npass*64 + r
            {
                const uint4* wsrc = (const uint4*)(g_wcv + (tap * CC + npass * 64) * CC);
                for (int idx = t; idx < 1024; idx += 256) {
                    int r = idx >> 4, ch16 = idx & 15;
                    *(uint4*)(smem + OFF_WST + r * PITCH + ch16 * 16) = wsrc[r * 16 + ch16];
                }
            }
            __syncthreads();

            int dy = tap / 3 - 1, dx = tap - (tap / 3) * 3 - 1;
            int delta = dy * 22 + dx;
            uint32_t abase = r1addr + (uint32_t)((23 + delta + w * 64 + lrow) * PITCH + lcol * 16);
            uint32_t bbase = wstaddr + (uint32_t)(brow * PITCH + bcol);

            #pragma unroll 2
            for (int k16 = 0; k16 < 8; k16++) {
                unsigned af[4][4], bf[4][4];
                #pragma unroll
                for (int mf = 0; mf < 4; mf++)
                    ldsm_x4(af[mf], abase + mf * 16 * PITCH + k16 * 32);
                #pragma unroll
                for (int ng = 0; ng < 4; ng++)
                    ldsm_x4(bf[ng], bbase + ng * 16 * PITCH + k16 * 32);
                #pragma unroll
                for (int mf = 0; mf < 4; mf++)
                    #pragma unroll
                    for (int nf = 0; nf < 8; nf++)
                        mma16816(acc[mf][nf], af[mf], &bf[nf >> 1][(nf & 1) * 2]);
            }
        }

        // epilogue: +bias -> silu -> *w3 -> reduce over n
        if (npass == 1) bias3 = b3s[0];
        float rs[4][2];
        #pragma unroll
        for (int mf = 0; mf < 4; mf++) { rs[mf][0] = 0.f; rs[mf][1] = 0.f; }
        #pragma unroll
        for (int nf = 0; nf < 8; nf++) {
            int c2 = npass * 64 + nf * 8 + (lane & 3) * 2;
            float wa = w3s[c2], wb = w3s[c2 + 1];
            float ba = br2s[c2], bb = br2s[c2 + 1];
            #pragma unroll
            for (int mf = 0; mf < 4; mf++) {
                rs[mf][0] += wa * lut_silu(lutp, acc[mf][nf][0] + ba)
                           + wb * lut_silu(lutp, acc[mf][nf][1] + bb);
                rs[mf][1] += wa * lut_silu(lutp, acc[mf][nf][2] + ba)
                           + wb * lut_silu(lutp, acc[mf][nf][3] + bb);
            }
        }
        #pragma unroll
        for (int mf = 0; mf < 4; mf++) {
            #pragma unroll
            for (int h = 0; h < 2; h++) {
                float v = rs[mf][h];
                v += __shfl_xor_sync(0xFFFFFFFF, v, 1);
                v += __shfl_xor_sync(0xFFFFFFFF, v, 2);
                if ((lane & 3) == 0) {
                    int m0 = w * 64 + mf * 16 + (lane >> 2) + h * 8;
                    if (npass == 0) {
                        part[m0] = v;
                    } else {
                        if (m0 < 484) {
                            int y = m0 / 22, xx = m0 - y * 22;
                            if (y >= 1 && y < 21 && xx >= 1 && xx < 21) {
                                int p = (y - 1) * 20 + (xx - 1);
                                float sc = bias3 + part[m0] + v;
                                g_scores[(b * CHW + nb) * CHW + p] = lut_silu(lutp, sc);
                            }
                        }
                    }
                }
            }
        }
    }
}

// ======================= K4: att + CBS2 + residual =======================
__global__ __launch_bounds__(128) void att_kernel(const float* __restrict__ x,
                                                  float* __restrict__ out) {
    __shared__ float sc[CHW];
    __shared__ float at[CC];
    int bi = blockIdx.x;
    int b = bi / CHW; int i = bi - b * CHW;
    int t = threadIdx.x;
    for (int j = t; j < CHW; j += 128) sc[j] = g_scores[bi * CHW + j];
    __syncthreads();
    float acc = 0.f;
    const float* fb = g_feat + b * CHW * CC;
    #pragma unroll 4
    for (int j = 0; j < CHW; j++) acc += sc[j] * fb[j * CC + t];
    at[t] = acc;
    __syncthreads();
    float o = g_bias2[t];
    #pragma unroll 8
    for (int k = 0; k < CC; k++) o += g_w2t[k * CC + t] * at[k];
    int oi = (b * CC + t) * CHW + i;
    out[oi] = siluf(o) + x[oi];
}

// ======================= launch =======================
extern "C" void kernel_launch(void* const* d_in, const int* in_sizes, int n_in,
                              void* d_out, int out_size) {
    (void)in_sizes; (void)n_in; (void)out_size;
    Params P;
    for (int i = 0; i < 26; i++) P.p[i] = (const float*)d_in[i];
    const float* x = (const float*)d_in[0];
    float* out = (float*)d_out;

    fold_kernel<<<64, 256>>>(P);
    a0_kernel<<<200, 128>>>();
    feat_kernel<<<CB * CHW, 128>>>(x);
    relation_fi_kernel<<<CB * 200, 256>>>();

    cudaFuncSetAttribute(relation_fj_mma_kernel,
                         cudaFuncAttributeMaxDynamicSharedMemorySize, FJ_SMEM);
    relation_fj_mma_kernel<<<CB * 200, 256, FJ_SMEM>>>();

    att_kernel<<<CB * CHW, 128>>>(x, out);
}